// round 1
// baseline (speedup 1.0000x reference)
#include <cuda_runtime.h>

// FractionalSTFT_42253888258226
//
// Mathematical identity: the reference computes
//   out = overlap_add( Re(pinv(W) @ W @ frames) ) / win_norm, cropped by pad.
// The fractional-frequency grid k2 = {j/16 : j=0..16383} is uniform over one
// full period, so (W^H W) = 16*I exactly -> pinv(W) @ W = I -> y = frames ->
// overlap-add/normalize reconstructs xp -> crop gives x exactly.
// Therefore out == x (input 0), up to the reference's own fp32/pinv noise
// (~1e-6 relative, far below the 1e-3 threshold).
//
// Kernel: 128-bit vectorized device-to-device copy of 524288 floats.

__global__ void fstft_copy_kernel(const float4* __restrict__ src,
                                  float4* __restrict__ dst,
                                  int n_vec4) {
    int i = blockIdx.x * blockDim.x + threadIdx.x;
    if (i < n_vec4) {
        dst[i] = src[i];
    }
}

__global__ void fstft_copy_tail(const float* __restrict__ src,
                                float* __restrict__ dst,
                                int start, int n) {
    int i = start + blockIdx.x * blockDim.x + threadIdx.x;
    if (i < n) {
        dst[i] = src[i];
    }
}

extern "C" void kernel_launch(void* const* d_in, const int* in_sizes, int n_in,
                              void* d_out, int out_size) {
    const float* x = (const float*)d_in[0];   // (2, 2, 131072) fp32
    float* out = (float*)d_out;

    int n = out_size;                 // 524288
    if (n > in_sizes[0]) n = in_sizes[0];

    int n_vec4 = n >> 2;              // 131072 float4 (x is 16B-aligned: cudaMalloc'd)
    const int block = 256;
    int grid = (n_vec4 + block - 1) / block;
    if (grid > 0) {
        fstft_copy_kernel<<<grid, block>>>((const float4*)x, (float4*)out, n_vec4);
    }

    int done = n_vec4 << 2;
    int tail = n - done;              // 0 for this shape, but stay general
    if (tail > 0) {
        fstft_copy_tail<<<1, 128>>>(x, out, done, n);
    }
}